// round 11
// baseline (speedup 1.0000x reference)
#include <cuda_runtime.h>
#include <cuda_bf16.h>
#include <cstdint>

// ESN: h_t = tanh(x_t @ W_in^T + h_{t-1} @ W_res^T); out = h_{T-1} [B,H] fp32.
// B=64, T=512, I=128, H=2048.
//
// Round 11: round-9 chassis (persistent 144 CTAs, 3-term bf16 mma.sync,
// 16 warps 16j x 32b, W in smem) with:
//  - ticket (atom.add.acq_rel) last-arriver reduce per jg (no reducer wake hop)
//  - h stored transposed [j][b]: reducer writes with no transpose, stager
//    reads contiguous, B frags via ldmatrix.x4.trans on k-major v rows
//  - P & h ping-pong; WAR closed by own-jg flag wait (no scnt).

#define BB   64
#define TT   512
#define II   128
#define HH   2048
#define NJG  16
#define NKS  9
#define KC1  256
#define NTHR 512
#define NCTA (NJG * NKS)          // 144
#define ASTRIDE 528               // bytes per j-row of W tiles (512 + 16 pad)
#define TSZA (128 * ASTRIDE)      // 67584 per W term
#define BSTR 144                  // bytes per k-row of v (128 data + 16 pad)
#define TSZB (256 * BSTR)         // 36864 per v term (max 256 k-rows)
#define BOFF (2 * TSZA)
#define SLOT (2 * TSZA)
#define DYN_SMEM (2 * TSZA + 2 * TSZB)   // 208896

// ---------------- device globals ----------------
__device__ __align__(16) unsigned char  g_wt[NCTA * SLOT];
__device__ __align__(16) __nv_bfloat16  g_xth[TT * II * BB];   // x^T hi: [t][k][b]
__device__ __align__(16) __nv_bfloat16  g_xtl[TT * II * BB];   // x^T lo
__device__ __align__(16) __nv_bfloat16  g_hth[2][HH * BB];     // h^T hi: [j][b]
__device__ __align__(16) __nv_bfloat16  g_htl[2][HH * BB];     // h^T lo
__device__ float    g_part[2][NKS * NJG * 128 * BB];           // ping-pong by t&1
__device__ unsigned g_tick[NJG];   // monotonic producer tickets (9/step)
__device__ unsigned g_hfl[NJG];    // h jg-tile ready flags (1/step)

// ---------------- asm helpers ----------------
__device__ __forceinline__ void mma_bf16(float* d, const uint32_t* a,
                                         uint32_t b0, uint32_t b1) {
    asm volatile(
        "mma.sync.aligned.m16n8k16.row.col.f32.bf16.bf16.f32 "
        "{%0,%1,%2,%3}, {%4,%5,%6,%7}, {%8,%9}, {%0,%1,%2,%3};"
        : "+f"(d[0]), "+f"(d[1]), "+f"(d[2]), "+f"(d[3])
        : "r"(a[0]), "r"(a[1]), "r"(a[2]), "r"(a[3]), "r"(b0), "r"(b1));
}
__device__ __forceinline__ void ldmx4(uint32_t* r, uint32_t addr) {
    asm volatile("ldmatrix.sync.aligned.m8n8.x4.shared.b16 {%0,%1,%2,%3}, [%4];"
        : "=r"(r[0]), "=r"(r[1]), "=r"(r[2]), "=r"(r[3]) : "r"(addr));
}
__device__ __forceinline__ void ldmx4t(uint32_t* r, uint32_t addr) {
    asm volatile("ldmatrix.sync.aligned.m8n8.x4.trans.shared.b16 {%0,%1,%2,%3}, [%4];"
        : "=r"(r[0]), "=r"(r[1]), "=r"(r[2]), "=r"(r[3]) : "r"(addr));
}
__device__ __forceinline__ uint32_t smem_u32(const void* p) {
    uint32_t a;
    asm("{ .reg .u64 t; cvta.to.shared.u64 t, %1; cvt.u32.u64 %0, t; }"
        : "=r"(a) : "l"(p));
    return a;
}
__device__ __forceinline__ void flag_add(unsigned* p) {
    asm volatile("red.release.gpu.global.add.u32 [%0], 1;" :: "l"(p) : "memory");
}
__device__ __forceinline__ unsigned ticket_add(unsigned* p) {
    unsigned old;
    asm volatile("atom.add.acq_rel.gpu.global.u32 %0, [%1], 1;"
                 : "=r"(old) : "l"(p) : "memory");
    return old;
}
__device__ __forceinline__ void spin_ge(unsigned* c, unsigned tgt) {
    unsigned v;
    do {
        asm volatile("ld.acquire.gpu.global.u32 %0, [%1];"
                     : "=r"(v) : "l"(c) : "memory");
    } while (v < tgt);
}

// ---------------- prep ----------------
__global__ void esn_prep_w(const float* __restrict__ Win, const float* __restrict__ Wres) {
    const int total = HH * (II + HH);
    for (int idx = blockIdx.x * blockDim.x + threadIdx.x; idx < total;
         idx += gridDim.x * blockDim.x) {
        int j = idx / (II + HH);
        int k = idx % (II + HH);
        int jg = j >> 7, jl = j & 127;
        int ks, kl;
        float w;
        if (k < II) { ks = 0; kl = k; w = Win[j * II + k]; }
        else { int kk = k - II; ks = 1 + (kk >> 8); kl = kk & 255; w = Wres[j * HH + kk]; }
        __nv_bfloat16 hi = __float2bfloat16(w);
        float r = w - __bfloat162float(hi);
        __nv_bfloat16 lo = __float2bfloat16(r);
        unsigned base = (unsigned)(jg * NKS + ks) * SLOT + (unsigned)jl * ASTRIDE + (unsigned)kl * 2;
        *(__nv_bfloat16*)(g_wt + base)        = hi;
        *(__nv_bfloat16*)(g_wt + base + TSZA) = lo;
    }
}

// x -> transposed [t][k][b] bf16 hi/lo planes
__global__ void esn_prep_x(const float* __restrict__ x) {
    const int total = TT * II * BB;
    for (int idx = blockIdx.x * blockDim.x + threadIdx.x; idx < total;
         idx += gridDim.x * blockDim.x) {
        int b  = idx & (BB - 1);
        int tk = idx / BB;
        int t  = tk / II;
        int k  = tk % II;
        float v = x[(b * TT + t) * II + k];
        __nv_bfloat16 hi = __float2bfloat16(v);
        float r = v - __bfloat162float(hi);
        g_xth[idx] = hi;
        g_xtl[idx] = __float2bfloat16(r);
    }
}

__global__ void esn_cnt0() {
    int i = threadIdx.x;
    if (i < NJG) { g_tick[i] = 0u; g_hfl[i] = 0u; }
}

// ---------------- persistent kernel ----------------
__global__ __launch_bounds__(NTHR, 1) void esn_run(float* __restrict__ out) {
    extern __shared__ __align__(16) unsigned char sm[];
    __shared__ unsigned sRed;

    const int tid  = threadIdx.x;
    const int wid  = tid >> 5;
    const int l    = tid & 31;
    const int wj   = wid >> 1;            // 0..7: 16-row j band
    const int wb   = wid & 1;             // 0..1: 32-col b half
    const int bid  = blockIdx.x;
    const int jg   = bid / NKS;
    const int ks   = bid % NKS;
    const int KC   = ks ? KC1 : II;
    const int kch  = KC >> 4;
    const int rows = KC;                  // v rows (k-major)
    const int chunks = rows * 8;          // 16B chunks (8 per 128B row)

    const uint32_t smA = smem_u32(sm);
    const uint32_t smB = smA + BOFF;

    // A ldmatrix lane base (normal, [j][k] rows)
    const uint32_t aA = smA + (uint32_t)(wj * 16 + ((l >> 3) & 1) * 8 + (l & 7)) * ASTRIDE
                            + (uint32_t)(l >> 4) * 16;
    // B ldmatrix.trans lane base ([k][b] rows): row = (l&7) + ((l>>3)&1)*8,
    // b-col byte = (l>>4)*16, + warp b-half offset wb*64B
    const uint32_t aB = smB + (uint32_t)((l & 7) + ((l >> 3) & 1) * 8) * BSTR
                            + (uint32_t)(l >> 4) * 16 + (uint32_t)wb * 64;

    // ---- load W slot (hi + lo) into smem once ----
    {
        const uint4* src = (const uint4*)(g_wt + (unsigned)(jg * NKS + ks) * SLOT);
        uint4* dst = (uint4*)sm;
        for (int i = tid; i < SLOT / 16; i += NTHR) dst[i] = src[i];
    }

    // reduce-role constants (ticket winner): thread owns 16 outputs
    const int r_jl = tid >> 2;            // 0..127
    const int r_b0 = (tid & 3) * 16;      // 0,16,32,48

    // ---- stage v_0: ks==0 from x^T[0], else zeros (h_{-1} = 0) ----
    if (ks == 0) {
        for (int i = tid; i < chunks; i += NTHR) {
            int k = i >> 3, c = i & 7;
            uint32_t d = (uint32_t)(BOFF + k * BSTR + c * 16);
            int e = k * BB + c * 8;       // t=0 base
            *(uint4*)(sm + d)        = *(const uint4*)(g_xth + e);
            *(uint4*)(sm + d + TSZB) = *(const uint4*)(g_xtl + e);
        }
    } else {
        const uint4 z = make_uint4(0u, 0u, 0u, 0u);
        for (int i = tid; i < chunks; i += NTHR) {
            int k = i >> 3, c = i & 7;
            uint32_t d = (uint32_t)(BOFF + k * BSTR + c * 16);
            *(uint4*)(sm + d)        = z;
            *(uint4*)(sm + d + TSZB) = z;
        }
    }
    __syncthreads();

    for (int t = 0; t < TT; t++) {
        // ---- MMA: warp = 16j x 32b; 3 terms (Ah*Bh + Ah*Bl + Al*Bh) ----
        float acc[4][4];
#pragma unroll
        for (int nf = 0; nf < 4; nf++)
#pragma unroll
            for (int i = 0; i < 4; i++) acc[nf][i] = 0.0f;

#pragma unroll 4
        for (int kc = 0; kc < kch; kc++) {
            const uint32_t kaA = (uint32_t)kc * 32;        // A: 16 k * 2B
            const uint32_t kaB = (uint32_t)kc * (16 * BSTR);
            uint32_t Ah[4], Al[4], Bh[2][4], Bl[2][4];
            ldmx4(Ah, aA + kaA);
            ldmx4(Al, aA + TSZA + kaA);
            ldmx4t(Bh[0], aB + kaB);                       // b 0-15 of half
            ldmx4t(Bh[1], aB + kaB + 32);                  // b 16-31
            ldmx4t(Bl[0], aB + TSZB + kaB);
            ldmx4t(Bl[1], aB + TSZB + kaB + 32);
#pragma unroll
            for (int nf = 0; nf < 4; nf++) {
                const int ni = nf >> 1, h8 = (nf & 1) * 2;
                mma_bf16(acc[nf], Ah, Bh[ni][h8], Bh[ni][h8 + 1]);
                mma_bf16(acc[nf], Ah, Bl[ni][h8], Bl[ni][h8 + 1]);
                mma_bf16(acc[nf], Al, Bh[ni][h8], Bh[ni][h8 + 1]);
            }
        }

        // ---- partial stores (.cg) into ping-pong buffer: P[jl*64 + b] ----
        {
            float* P = g_part[t & 1] + (unsigned)(ks * NJG + jg) * (128 * BB);
            const int j0 = wj * 16 + (l >> 2);
            const int bc = (l & 3) * 2;
#pragma unroll
            for (int nf = 0; nf < 4; nf++) {
                const int b = wb * 32 + nf * 8 + bc;
                __stcg((float2*)&P[j0 * BB + b],       make_float2(acc[nf][0], acc[nf][1]));
                __stcg((float2*)&P[(j0 + 8) * BB + b], make_float2(acc[nf][2], acc[nf][3]));
            }
        }
        __syncthreads();                        // all P stores + all v reads done

        // ---- ticket: 9th arriver of this jg reduces the whole jg tile ----
        if (tid == 0) {
            unsigned old = ticket_add(&g_tick[jg]);
            sRed = (old == (unsigned)(NKS * t + NKS - 1)) ? 1u : 0u;
        }
        __syncthreads();

        if (sRed) {
            const float* Pb = g_part[t & 1];
            float s[16];
#pragma unroll
            for (int i = 0; i < 16; i++) s[i] = 0.0f;
            const unsigned o = (unsigned)(r_jl * BB + r_b0);
#pragma unroll
            for (int kr = 0; kr < NKS; kr++) {
                const float4* q = (const float4*)(Pb + (unsigned)(kr * NJG + jg) * (128 * BB) + o);
#pragma unroll
                for (int m = 0; m < 4; m++) {
                    const float4 v = __ldcg(q + m);
                    s[m * 4 + 0] += v.x; s[m * 4 + 1] += v.y;
                    s[m * 4 + 2] += v.z; s[m * 4 + 3] += v.w;
                }
            }
#pragma unroll
            for (int i = 0; i < 16; i++) s[i] = tanhf(s[i]);

            // write h^T [j][b]: 16 contiguous b per thread, hi & lo planes
            __nv_bfloat16* hh = g_hth[t & 1];
            __nv_bfloat16* hl = g_htl[t & 1];
            const unsigned ho = (unsigned)((jg * 128 + r_jl) * BB + r_b0);
            uint32_t hip[8], lop[8];
#pragma unroll
            for (int p = 0; p < 8; p++) {
                __nv_bfloat162 h2 = __floats2bfloat162_rn(s[2 * p], s[2 * p + 1]);
                float r0 = s[2 * p]     - __bfloat162float(__low2bfloat16(h2));
                float r1 = s[2 * p + 1] - __bfloat162float(__high2bfloat16(h2));
                __nv_bfloat162 l2 = __floats2bfloat162_rn(r0, r1);
                hip[p] = *(uint32_t*)&h2;
                lop[p] = *(uint32_t*)&l2;
            }
            __stcg((uint4*)(hh + ho),     make_uint4(hip[0], hip[1], hip[2], hip[3]));
            __stcg((uint4*)(hh + ho + 8), make_uint4(hip[4], hip[5], hip[6], hip[7]));
            __stcg((uint4*)(hl + ho),     make_uint4(lop[0], lop[1], lop[2], lop[3]));
            __stcg((uint4*)(hl + ho + 8), make_uint4(lop[4], lop[5], lop[6], lop[7]));

            if (t == TT - 1) {
                const int jglob = jg * 128 + r_jl;
#pragma unroll
                for (int i = 0; i < 16; i++)
                    out[(r_b0 + i) * HH + jglob] = s[i];
            }
            __syncthreads();                    // all h stores before flag
            if (tid == 0) flag_add(&g_hfl[jg]);
        }

        // ---- stage v_{t+1} ----
        if (t + 1 < TT) {
            if (tid == 0) {
                const unsigned u = (unsigned)(t + 1);
                if (t >= 1) spin_ge(&g_hfl[jg], u - 0);    // own reduce(t) done? see below
                // own-jg WAR (reduce(t-1) done before P[(t+1)&1] overwrite):
                // covered by >= u-1; but we also must not overwrite P[t&1] later;
                // chain closed by waiting own flag to u-1:
                // (use u-1; for consumers use u)
                if (ks) {
                    spin_ge(&g_hfl[2 * (ks - 1)],     u);  // h_t slice ready
                    spin_ge(&g_hfl[2 * (ks - 1) + 1], u);
                }
            }
            __syncthreads();

            if (ks == 0) {
                const __nv_bfloat16* xh = g_xth + (t + 1) * (II * BB);
                const __nv_bfloat16* xl = g_xtl + (t + 1) * (II * BB);
                for (int i = tid; i < chunks; i += NTHR) {
                    int k = i >> 3, c = i & 7;
                    uint32_t d = (uint32_t)(BOFF + k * BSTR + c * 16);
                    int e = k * BB + c * 8;
                    *(uint4*)(sm + d)        = *(const uint4*)(xh + e);
                    *(uint4*)(sm + d + TSZB) = *(const uint4*)(xl + e);
                }
            } else {
                const __nv_bfloat16* hh = g_hth[t & 1] + (ks - 1) * (KC1 * BB);
                const __nv_bfloat16* hl = g_htl[t & 1] + (ks - 1) * (KC1 * BB);
                for (int i = tid; i < chunks; i += NTHR) {
                    int k = i >> 3, c = i & 7;
                    uint32_t d = (uint32_t)(BOFF + k * BSTR + c * 16);
                    int e = k * BB + c * 8;
                    *(uint4*)(sm + d)        = __ldcg((const uint4*)(hh + e));
                    *(uint4*)(sm + d + TSZB) = __ldcg((const uint4*)(hl + e));
                }
            }
            __syncthreads();                    // v staged before next MMA
        }
    }
}

// ---------------- launcher ----------------
extern "C" void kernel_launch(void* const* d_in, const int* in_sizes, int n_in,
                              void* d_out, int out_size)
{
    const float* x    = (const float*)d_in[0];
    const float* Win  = (const float*)d_in[1];
    const float* Wres = (const float*)d_in[2];
    float* out = (float*)d_out;

    cudaFuncSetAttribute(esn_run, cudaFuncAttributeMaxDynamicSharedMemorySize, DYN_SMEM);

    esn_prep_w<<<2048, 256>>>(Win, Wres);
    esn_prep_x<<<2048, 256>>>(x);
    esn_cnt0<<<1, 32>>>();
    esn_run<<<NCTA, NTHR, DYN_SMEM>>>(out);
}

// round 12
// speedup vs baseline: 1.7099x; 1.7099x over previous
#include <cuda_runtime.h>
#include <cuda_bf16.h>
#include <cstdint>

// ESN: h_t = tanh(x_t @ W_in^T + h_{t-1} @ W_res^T); out = h_{T-1} [B,H] fp32.
// B=64, T=512, I=128, H=2048.
//
// Round 12: round-9 chassis (persistent 144 CTAs, 3-term bf16 mma.sync,
// 16 warps 16j x 32b, W in smem, wide 128-CTA reduce, P ping-pong) +
// pipelined h staging: per-jg flags (16 x 8 arrivals); tail stages only
// chunk1 (first 128 h rows of the slice); next iteration runs MMA kc0-7,
// stages chunk2 mid-loop, then runs kc8-15.

#define BB   64
#define TT   512
#define II   128
#define HH   2048
#define NJG  16
#define NKS  9
#define KC1  256
#define NTHR 512
#define NCTA (NJG * NKS)          // 144
#define ASTRIDE 528               // bytes per j-row (512 data + 16 pad)
#define TSZA (128 * ASTRIDE)      // 67584 per W term
#define BSTRIDE 528
#define TSZB (BB * BSTRIDE)       // 33792 per v term
#define BOFF (2 * TSZA)
#define SLOT (2 * TSZA)
#define DYN_SMEM (2 * TSZA + 2 * TSZB)   // 202752

// ---------------- device globals ----------------
__device__ __align__(16) unsigned char  g_wt[NCTA * SLOT];
__device__ __align__(16) __nv_bfloat16  g_xh[BB * TT * II];
__device__ __align__(16) __nv_bfloat16  g_xl[BB * TT * II];
__device__ __align__(16) __nv_bfloat16  g_hh[2][BB * HH];
__device__ __align__(16) __nv_bfloat16  g_hl[2][BB * HH];
__device__ float    g_part[2][NKS * NJG * 128 * BB];   // ping-pong by t&1
__device__ unsigned g_pcnt[NJG];   // partials stored, per jg (9/step)
__device__ unsigned g_hfl[NJG];    // h jg-tile ready, per jg (8/step)

// ---------------- asm helpers ----------------
__device__ __forceinline__ void mma_bf16(float* d, const uint32_t* a,
                                         uint32_t b0, uint32_t b1) {
    asm volatile(
        "mma.sync.aligned.m16n8k16.row.col.f32.bf16.bf16.f32 "
        "{%0,%1,%2,%3}, {%4,%5,%6,%7}, {%8,%9}, {%0,%1,%2,%3};"
        : "+f"(d[0]), "+f"(d[1]), "+f"(d[2]), "+f"(d[3])
        : "r"(a[0]), "r"(a[1]), "r"(a[2]), "r"(a[3]), "r"(b0), "r"(b1));
}
__device__ __forceinline__ void ldmx4(uint32_t* r, uint32_t addr) {
    asm volatile("ldmatrix.sync.aligned.m8n8.x4.shared.b16 {%0,%1,%2,%3}, [%4];"
        : "=r"(r[0]), "=r"(r[1]), "=r"(r[2]), "=r"(r[3]) : "r"(addr));
}
__device__ __forceinline__ uint32_t smem_u32(const void* p) {
    uint32_t a;
    asm("{ .reg .u64 t; cvta.to.shared.u64 t, %1; cvt.u32.u64 %0, t; }"
        : "=r"(a) : "l"(p));
    return a;
}
__device__ __forceinline__ void flag_add(unsigned* p) {
    asm volatile("red.release.gpu.global.add.u32 [%0], 1;" :: "l"(p) : "memory");
}
__device__ __forceinline__ void spin_ge(unsigned* c, unsigned tgt) {
    unsigned v;
    do {
        asm volatile("ld.acquire.gpu.global.u32 %0, [%1];"
                     : "=r"(v) : "l"(c) : "memory");
    } while (v < tgt);
}

// ---------------- prep ----------------
__global__ void esn_prep_w(const float* __restrict__ Win, const float* __restrict__ Wres) {
    const int total = HH * (II + HH);
    for (int idx = blockIdx.x * blockDim.x + threadIdx.x; idx < total;
         idx += gridDim.x * blockDim.x) {
        int j = idx / (II + HH);
        int k = idx % (II + HH);
        int jg = j >> 7, jl = j & 127;
        int ks, kl;
        float w;
        if (k < II) { ks = 0; kl = k; w = Win[j * II + k]; }
        else { int kk = k - II; ks = 1 + (kk >> 8); kl = kk & 255; w = Wres[j * HH + kk]; }
        __nv_bfloat16 hi = __float2bfloat16(w);
        float r = w - __bfloat162float(hi);
        __nv_bfloat16 lo = __float2bfloat16(r);
        unsigned base = (unsigned)(jg * NKS + ks) * SLOT + (unsigned)jl * ASTRIDE + (unsigned)kl * 2;
        *(__nv_bfloat16*)(g_wt + base)        = hi;
        *(__nv_bfloat16*)(g_wt + base + TSZA) = lo;
    }
}

__global__ void esn_prep_x(const float* __restrict__ x) {
    const int total = BB * TT * II;
    for (int idx = blockIdx.x * blockDim.x + threadIdx.x; idx < total;
         idx += gridDim.x * blockDim.x) {
        float v = x[idx];
        __nv_bfloat16 hi = __float2bfloat16(v);
        float r = v - __bfloat162float(hi);
        g_xh[idx] = hi;
        g_xl[idx] = __float2bfloat16(r);
    }
}

__global__ void esn_cnt0() {
    int i = threadIdx.x;
    if (i < NJG) { g_pcnt[i] = 0u; g_hfl[i] = 0u; }
}

// ---------------- persistent kernel ----------------
__global__ __launch_bounds__(NTHR, 1) void esn_run(float* __restrict__ out) {
    extern __shared__ __align__(16) unsigned char sm[];
    __shared__ float sT[16 * 65];

    const int tid  = threadIdx.x;
    const int wid  = tid >> 5;
    const int l    = tid & 31;
    const int wj   = wid >> 1;            // 0..7: 16-row j band
    const int wb   = wid & 1;             // 0..1: 32-col b half
    const int bid  = blockIdx.x;
    const int jg   = bid / NKS;
    const int ks   = bid % NKS;
    const int KC   = ks ? KC1 : II;
    const int kch  = KC >> 4;             // 8 or 16
    const int kchA = 8;                   // first-half kc count (all of ks=0)
    const int cpb  = KC >> 3;             // 16B chunks per b-row (16 or 32)

    const uint32_t smA = smem_u32(sm);
    const uint32_t smB = smA + BOFF;

    // ldmatrix lane bases
    const uint32_t aA = smA + (uint32_t)(wj * 16 + ((l >> 3) & 1) * 8 + (l & 7)) * ASTRIDE
                            + (uint32_t)(l >> 4) * 16;
    const uint32_t aB = smB + (uint32_t)(wb * 32 + ((l >> 4) & 1) * 8 + (l & 7)) * BSTRIDE
                            + (uint32_t)((l >> 3) & 1) * 16;

    // ---- load W slot (hi + lo) into smem once ----
    {
        const uint4* src = (const uint4*)(g_wt + (unsigned)(jg * NKS + ks) * SLOT);
        uint4* dst = (uint4*)sm;
        for (int i = tid; i < SLOT / 16; i += NTHR) dst[i] = src[i];
    }

    // reduce-role constants (bid 0..127): 16j x 64b tile
    const int r_jg = bid >> 3;
    const int r_8  = bid & 7;
    const int jt   = tid >> 5;             // 0..15
    const int b2   = (tid & 31) * 2;       // 0..62

    // ---- stage v_0 fully: ks==0 from x[0], else zeros (h_{-1} = 0) ----
    if (ks == 0) {
        for (int i = tid; i < BB * 16; i += NTHR) {
            int b = i >> 4, c = i & 15;
            int e = (b * TT + 0) * II + c * 8;
            uint32_t d = (uint32_t)(BOFF + b * BSTRIDE + c * 16);
            *(uint4*)(sm + d)        = *(const uint4*)(g_xh + e);
            *(uint4*)(sm + d + TSZB) = *(const uint4*)(g_xl + e);
        }
    } else {
        const uint4 z = make_uint4(0u, 0u, 0u, 0u);
        for (int i = tid; i < BB * cpb; i += NTHR) {
            int b = i / cpb, c = i - b * cpb;
            uint32_t d = (uint32_t)(BOFF + b * BSTRIDE + c * 16);
            *(uint4*)(sm + d)        = z;
            *(uint4*)(sm + d + TSZB) = z;
        }
    }
    __syncthreads();

    for (int t = 0; t < TT; t++) {
        float acc[4][4];
#pragma unroll
        for (int nf = 0; nf < 4; nf++)
#pragma unroll
            for (int i = 0; i < 4; i++) acc[nf][i] = 0.0f;

        // ---- MMA first half: kc 0..7 (chunk1 of v_t) ----
#pragma unroll 4
        for (int kc = 0; kc < kchA; kc++) {
            const uint32_t ka = (uint32_t)kc * 32;
            uint32_t Ah[4], Al[4], Bh[2][4], Bl[2][4];
            ldmx4(Ah, aA + ka);
            ldmx4(Al, aA + TSZA + ka);
            ldmx4(Bh[0], aB + ka);
            ldmx4(Bh[1], aB + 16 * BSTRIDE + ka);
            ldmx4(Bl[0], aB + TSZB + ka);
            ldmx4(Bl[1], aB + TSZB + 16 * BSTRIDE + ka);
#pragma unroll
            for (int nf = 0; nf < 4; nf++) {
                const int ni = nf >> 1, h8 = (nf & 1) * 2;
                mma_bf16(acc[nf], Ah, Bh[ni][h8], Bh[ni][h8 + 1]);
                mma_bf16(acc[nf], Ah, Bl[ni][h8], Bl[ni][h8 + 1]);
                mma_bf16(acc[nf], Al, Bh[ni][h8], Bh[ni][h8 + 1]);
            }
        }

        // ---- mid-iter: stage chunk2 of v_t (h rows 128..255 of slice), ks>=1, t>=1 ----
        if (ks && t >= 1) {
            if (tid == 0) spin_ge(&g_hfl[2 * (ks - 1) + 1], 8u * t);  // reduce(t-1) jg 2s+1
            __syncthreads();
            const __nv_bfloat16* hh = g_hh[(t - 1) & 1];
            const __nv_bfloat16* hl = g_hl[(t - 1) & 1];
            for (int i = tid; i < BB * 16; i += NTHR) {
                int b = i >> 4, c = 16 + (i & 15);
                int e = b * HH + (ks - 1) * KC1 + c * 8;
                uint32_t d = (uint32_t)(BOFF + b * BSTRIDE + c * 16);
                *(uint4*)(sm + d)        = __ldcg((const uint4*)(hh + e));
                *(uint4*)(sm + d + TSZB) = __ldcg((const uint4*)(hl + e));
            }
            __syncthreads();
        }

        // ---- MMA second half: kc 8..15 (ks>=1 only) ----
        if (ks) {
#pragma unroll 4
            for (int kc = kchA; kc < 16; kc++) {
                const uint32_t ka = (uint32_t)kc * 32;
                uint32_t Ah[4], Al[4], Bh[2][4], Bl[2][4];
                ldmx4(Ah, aA + ka);
                ldmx4(Al, aA + TSZA + ka);
                ldmx4(Bh[0], aB + ka);
                ldmx4(Bh[1], aB + 16 * BSTRIDE + ka);
                ldmx4(Bl[0], aB + TSZB + ka);
                ldmx4(Bl[1], aB + TSZB + 16 * BSTRIDE + ka);
#pragma unroll
                for (int nf = 0; nf < 4; nf++) {
                    const int ni = nf >> 1, h8 = (nf & 1) * 2;
                    mma_bf16(acc[nf], Ah, Bh[ni][h8], Bh[ni][h8 + 1]);
                    mma_bf16(acc[nf], Ah, Bl[ni][h8], Bl[ni][h8 + 1]);
                    mma_bf16(acc[nf], Al, Bh[ni][h8], Bh[ni][h8 + 1]);
                }
            }
        }

        // ---- partial stores (.cg) into ping-pong buffer: P[jl*64 + b] ----
        {
            float* P = g_part[t & 1] + (unsigned)(ks * NJG + jg) * (128 * BB);
            const int j0 = wj * 16 + (l >> 2);
            const int bc = (l & 3) * 2;
#pragma unroll
            for (int nf = 0; nf < 4; nf++) {
                const int b = wb * 32 + nf * 8 + bc;
                __stcg((float2*)&P[j0 * BB + b],       make_float2(acc[nf][0], acc[nf][1]));
                __stcg((float2*)&P[(j0 + 8) * BB + b], make_float2(acc[nf][2], acc[nf][3]));
            }
        }
        __syncthreads();                        // all P stores + all v reads done
        if (tid == 0) flag_add(&g_pcnt[jg]);

        // ---- reduce role (bid 0..127): 16j x 64b tile ----
        if (bid < 128) {
            if (tid == 0) spin_ge(&g_pcnt[r_jg], 9u * (t + 1));
            __syncthreads();

            const unsigned o = (unsigned)((r_8 * 16 + jt) * 64 + b2);
            float s0 = 0.f, s1 = 0.f;
            const float* Pb = g_part[t & 1];
#pragma unroll
            for (int kr = 0; kr < NKS; kr++) {
                const float2 v = __ldcg((const float2*)
                    (Pb + (unsigned)(kr * NJG + r_jg) * (128 * BB) + o));
                s0 += v.x; s1 += v.y;
            }
            s0 = tanhf(s0); s1 = tanhf(s1);
            sT[jt * 65 + b2]     = s0;
            sT[jt * 65 + b2 + 1] = s1;
            __syncthreads();                    // transpose handoff

            __nv_bfloat16* hh = g_hh[t & 1];
            __nv_bfloat16* hl = g_hl[t & 1];
            const bool last_t = (t == TT - 1);
            {
                const int p  = tid & 7;         // j pair
                const int bb = tid >> 3;        // batch
                const float f0 = sT[(2 * p) * 65 + bb];
                const float f1 = sT[(2 * p + 1) * 65 + bb];
                const int jglob = r_jg * 128 + r_8 * 16 + 2 * p;
                __nv_bfloat162 h2 = __floats2bfloat162_rn(f0, f1);
                float r0 = f0 - __bfloat162float(__low2bfloat16(h2));
                float r1 = f1 - __bfloat162float(__high2bfloat16(h2));
                __nv_bfloat162 l2 = __floats2bfloat162_rn(r0, r1);
                __stcg((unsigned*)(hh + bb * HH + jglob), *(unsigned*)&h2);
                __stcg((unsigned*)(hl + bb * HH + jglob), *(unsigned*)&l2);
                if (last_t) *(float2*)&out[bb * HH + jglob] = make_float2(f0, f1);
            }
            __syncthreads();                    // all h stores done before flag
            if (tid == 0) flag_add(&g_hfl[r_jg]);
        }

        // ---- tail: stage v_{t+1} chunk1 (or full x) ----
        if (t + 1 < TT) {
            if (tid == 0) {
                // P WAR: reducers of my jg done reading P[(t+1)&1] (step t-1)
                if (t >= 1) spin_ge(&g_hfl[jg], 8u * t);
                // RAW: h_t chunk1 (jg 2(ks-1)) ready
                if (ks) spin_ge(&g_hfl[2 * (ks - 1)], 8u * (t + 1));
            }
            __syncthreads();

            if (ks == 0) {
                for (int i = tid; i < BB * 16; i += NTHR) {
                    int b = i >> 4, c = i & 15;
                    int e = (b * TT + (t + 1)) * II + c * 8;
                    uint32_t d = (uint32_t)(BOFF + b * BSTRIDE + c * 16);
                    *(uint4*)(sm + d)        = *(const uint4*)(g_xh + e);
                    *(uint4*)(sm + d + TSZB) = *(const uint4*)(g_xl + e);
                }
            } else {
                const __nv_bfloat16* hh = g_hh[t & 1];
                const __nv_bfloat16* hl = g_hl[t & 1];
                for (int i = tid; i < BB * 16; i += NTHR) {
                    int b = i >> 4, c = i & 15;     // chunk1: c 0..15
                    int e = b * HH + (ks - 1) * KC1 + c * 8;
                    uint32_t d = (uint32_t)(BOFF + b * BSTRIDE + c * 16);
                    *(uint4*)(sm + d)        = __ldcg((const uint4*)(hh + e));
                    *(uint4*)(sm + d + TSZB) = __ldcg((const uint4*)(hl + e));
                }
            }
            __syncthreads();                    // chunk1 staged before next MMA
        }
    }
}

// ---------------- launcher ----------------
extern "C" void kernel_launch(void* const* d_in, const int* in_sizes, int n_in,
                              void* d_out, int out_size)
{
    const float* x    = (const float*)d_in[0];
    const float* Win  = (const float*)d_in[1];
    const float* Wres = (const float*)d_in[2];
    float* out = (float*)d_out;

    cudaFuncSetAttribute(esn_run, cudaFuncAttributeMaxDynamicSharedMemorySize, DYN_SMEM);

    esn_prep_w<<<2048, 256>>>(Win, Wres);
    esn_prep_x<<<2048, 256>>>(x);
    esn_cnt0<<<1, 32>>>();
    esn_run<<<NCTA, NTHR, DYN_SMEM>>>(out);
}

// round 13
// speedup vs baseline: 1.7565x; 1.0272x over previous
#include <cuda_runtime.h>
#include <cuda_bf16.h>
#include <cstdint>

// ESN: h_t = tanh(x_t @ W_in^T + h_{t-1} @ W_res^T); out = h_{T-1} [B,H] fp32.
// B=64, T=512, I=128, H=2048.
//
// Round 13: round-9 chassis with the x-GEMM hoisted out of the recurrence.
// Prep computes xc[t] = x_t @ W_in^T for all t (2048-CTA pass, identical
// 3-term bf16 mma code -> bitwise-identical partials). Persistent loop:
// grid 128 = 16jg x 8ks, uniform K=256, reducers sum xc + 8 partials.

#define BB   64
#define TT   512
#define II   128
#define HH   2048
#define NJG  16
#define NKS  8
#define KC1  256
#define NTHR 512
#define NCTA (NJG * NKS)          // 128
#define ASTRIDE 528               // bytes per j-row (512 data + 16 pad)
#define TSZA (128 * ASTRIDE)      // 67584 per W term
#define BSTRIDE 528
#define TSZB (BB * BSTRIDE)       // 33792 per v term
#define BOFF (2 * TSZA)
#define SLOT (2 * TSZA)
#define DYN_SMEM (2 * TSZA + 2 * TSZB)   // 202752

// prep-GEMM (K=128) smem layout
#define AST2 272
#define TSA2 (128 * AST2)         // 34816
#define BST2 272
#define TSB2 (BB * BST2)          // 17408
#define BOFF2 (2 * TSA2)
#define DYN2 (2 * TSA2 + 2 * TSB2)   // 104448

// ---------------- device globals ----------------
__device__ __align__(16) unsigned char  g_wt[NCTA * SLOT];        // W_res slots
__device__ __align__(16) unsigned char  g_wi[NJG * 2 * TSA2];     // W_in slots
__device__ __align__(16) __nv_bfloat16  g_xh[BB * TT * II];
__device__ __align__(16) __nv_bfloat16  g_xl[BB * TT * II];
__device__ __align__(16) __nv_bfloat16  g_hh[2][BB * HH];
__device__ __align__(16) __nv_bfloat16  g_hl[2][BB * HH];
__device__ float    g_xc[TT * NJG * 128 * BB];                    // 256 MB
__device__ float    g_part[2][NKS * NJG * 128 * BB];              // ping-pong
__device__ unsigned g_pcnt[NJG];   // partials stored, per jg (8/step)
__device__ unsigned g_hfl[NJG];    // h jg-tile ready, per jg (8/step)

// ---------------- asm helpers ----------------
__device__ __forceinline__ void mma_bf16(float* d, const uint32_t* a,
                                         uint32_t b0, uint32_t b1) {
    asm volatile(
        "mma.sync.aligned.m16n8k16.row.col.f32.bf16.bf16.f32 "
        "{%0,%1,%2,%3}, {%4,%5,%6,%7}, {%8,%9}, {%0,%1,%2,%3};"
        : "+f"(d[0]), "+f"(d[1]), "+f"(d[2]), "+f"(d[3])
        : "r"(a[0]), "r"(a[1]), "r"(a[2]), "r"(a[3]), "r"(b0), "r"(b1));
}
__device__ __forceinline__ void ldmx4(uint32_t* r, uint32_t addr) {
    asm volatile("ldmatrix.sync.aligned.m8n8.x4.shared.b16 {%0,%1,%2,%3}, [%4];"
        : "=r"(r[0]), "=r"(r[1]), "=r"(r[2]), "=r"(r[3]) : "r"(addr));
}
__device__ __forceinline__ uint32_t smem_u32(const void* p) {
    uint32_t a;
    asm("{ .reg .u64 t; cvta.to.shared.u64 t, %1; cvt.u32.u64 %0, t; }"
        : "=r"(a) : "l"(p));
    return a;
}
__device__ __forceinline__ void flag_add(unsigned* p) {
    asm volatile("red.release.gpu.global.add.u32 [%0], 1;" :: "l"(p) : "memory");
}
__device__ __forceinline__ void spin_ge(unsigned* c, unsigned tgt) {
    unsigned v;
    do {
        asm volatile("ld.acquire.gpu.global.u32 %0, [%1];"
                     : "=r"(v) : "l"(c) : "memory");
    } while (v < tgt);
}

// ---------------- prep ----------------
__global__ void esn_prep_w(const float* __restrict__ Win, const float* __restrict__ Wres) {
    const int total = HH * (II + HH);
    for (int idx = blockIdx.x * blockDim.x + threadIdx.x; idx < total;
         idx += gridDim.x * blockDim.x) {
        int j = idx / (II + HH);
        int k = idx % (II + HH);
        int jg = j >> 7, jl = j & 127;
        if (k < II) {
            float w = Win[j * II + k];
            __nv_bfloat16 hi = __float2bfloat16(w);
            __nv_bfloat16 lo = __float2bfloat16(w - __bfloat162float(hi));
            unsigned base = (unsigned)jg * (2 * TSA2) + (unsigned)jl * AST2 + (unsigned)k * 2;
            *(__nv_bfloat16*)(g_wi + base)        = hi;
            *(__nv_bfloat16*)(g_wi + base + TSA2) = lo;
        } else {
            int kk = k - II;
            int ks = kk >> 8, kl = kk & 255;
            float w = Wres[j * HH + kk];
            __nv_bfloat16 hi = __float2bfloat16(w);
            __nv_bfloat16 lo = __float2bfloat16(w - __bfloat162float(hi));
            unsigned base = (unsigned)(jg * NKS + ks) * SLOT + (unsigned)jl * ASTRIDE + (unsigned)kl * 2;
            *(__nv_bfloat16*)(g_wt + base)        = hi;
            *(__nv_bfloat16*)(g_wt + base + TSZA) = lo;
        }
    }
}

__global__ void esn_prep_x(const float* __restrict__ x) {
    const int total = BB * TT * II;
    for (int idx = blockIdx.x * blockDim.x + threadIdx.x; idx < total;
         idx += gridDim.x * blockDim.x) {
        float v = x[idx];
        __nv_bfloat16 hi = __float2bfloat16(v);
        g_xh[idx] = hi;
        g_xl[idx] = __float2bfloat16(v - __bfloat162float(hi));
    }
}

// xc[t][jg] = x_t @ W_in^T tile, EXACT same 3-term mma code path as producers.
__global__ __launch_bounds__(NTHR, 1) void esn_prep_xc() {
    extern __shared__ __align__(16) unsigned char sm[];
    const int tid = threadIdx.x;
    const int wid = tid >> 5;
    const int l   = tid & 31;
    const int wj  = wid >> 1;
    const int wb  = wid & 1;
    const int t   = blockIdx.x >> 4;
    const int jg  = blockIdx.x & 15;

    const uint32_t smA = smem_u32(sm);
    const uint32_t smB = smA + BOFF2;
    const uint32_t aA = smA + (uint32_t)(wj * 16 + ((l >> 3) & 1) * 8 + (l & 7)) * AST2
                            + (uint32_t)(l >> 4) * 16;
    const uint32_t aB = smB + (uint32_t)(wb * 32 + ((l >> 4) & 1) * 8 + (l & 7)) * BST2
                            + (uint32_t)((l >> 3) & 1) * 16;

    {   // W_in slot
        const uint4* src = (const uint4*)(g_wi + (unsigned)jg * (2 * TSA2));
        uint4* dst = (uint4*)sm;
        for (int i = tid; i < (2 * TSA2) / 16; i += NTHR) dst[i] = src[i];
    }
    // stage x_t (hi/lo)
    for (int i = tid; i < BB * 16; i += NTHR) {
        int b = i >> 4, c = i & 15;
        int e = (b * TT + t) * II + c * 8;
        uint32_t d = (uint32_t)(BOFF2 + b * BST2 + c * 16);
        *(uint4*)(sm + d)        = *(const uint4*)(g_xh + e);
        *(uint4*)(sm + d + TSB2) = *(const uint4*)(g_xl + e);
    }
    __syncthreads();

    float acc[4][4];
#pragma unroll
    for (int nf = 0; nf < 4; nf++)
#pragma unroll
        for (int i = 0; i < 4; i++) acc[nf][i] = 0.0f;

#pragma unroll
    for (int kc = 0; kc < 8; kc++) {
        const uint32_t ka = (uint32_t)kc * 32;
        uint32_t Ah[4], Al[4], Bh[2][4], Bl[2][4];
        ldmx4(Ah, aA + ka);
        ldmx4(Al, aA + TSA2 + ka);
        ldmx4(Bh[0], aB + ka);
        ldmx4(Bh[1], aB + 16 * BST2 + ka);
        ldmx4(Bl[0], aB + TSB2 + ka);
        ldmx4(Bl[1], aB + TSB2 + 16 * BST2 + ka);
#pragma unroll
        for (int nf = 0; nf < 4; nf++) {
            const int ni = nf >> 1, h8 = (nf & 1) * 2;
            mma_bf16(acc[nf], Ah, Bh[ni][h8], Bh[ni][h8 + 1]);
            mma_bf16(acc[nf], Ah, Bl[ni][h8], Bl[ni][h8 + 1]);
            mma_bf16(acc[nf], Al, Bh[ni][h8], Bh[ni][h8 + 1]);
        }
    }

    float* X = g_xc + (unsigned)(t * NJG + jg) * (128 * BB);
    const int j0 = wj * 16 + (l >> 2);
    const int bc = (l & 3) * 2;
#pragma unroll
    for (int nf = 0; nf < 4; nf++) {
        const int b = wb * 32 + nf * 8 + bc;
        *(float2*)&X[j0 * BB + b]       = make_float2(acc[nf][0], acc[nf][1]);
        *(float2*)&X[(j0 + 8) * BB + b] = make_float2(acc[nf][2], acc[nf][3]);
    }
}

__global__ void esn_cnt0() {
    int i = threadIdx.x;
    if (i < NJG) { g_pcnt[i] = 0u; g_hfl[i] = 0u; }
}

// ---------------- persistent kernel ----------------
__global__ __launch_bounds__(NTHR, 1) void esn_run(float* __restrict__ out) {
    extern __shared__ __align__(16) unsigned char sm[];
    __shared__ float sT[16 * 65];

    const int tid  = threadIdx.x;
    const int wid  = tid >> 5;
    const int l    = tid & 31;
    const int wj   = wid >> 1;            // 0..7: 16-row j band
    const int wb   = wid & 1;             // 0..1: 32-col b half
    const int bid  = blockIdx.x;
    const int jg   = bid >> 3;
    const int ks   = bid & 7;

    const uint32_t smA = smem_u32(sm);
    const uint32_t smB = smA + BOFF;

    const uint32_t aA = smA + (uint32_t)(wj * 16 + ((l >> 3) & 1) * 8 + (l & 7)) * ASTRIDE
                            + (uint32_t)(l >> 4) * 16;
    const uint32_t aB = smB + (uint32_t)(wb * 32 + ((l >> 4) & 1) * 8 + (l & 7)) * BSTRIDE
                            + (uint32_t)((l >> 3) & 1) * 16;

    // ---- load W_res slot (hi + lo) into smem once ----
    {
        const uint4* src = (const uint4*)(g_wt + (unsigned)(jg * NKS + ks) * SLOT);
        uint4* dst = (uint4*)sm;
        for (int i = tid; i < SLOT / 16; i += NTHR) dst[i] = src[i];
    }

    // reduce-role constants: 16j x 64b tile
    const int r_jg = bid >> 3;
    const int r_8  = bid & 7;
    const int jt   = tid >> 5;             // 0..15
    const int b2   = (tid & 31) * 2;       // 0..62

    // ---- stage v_0 = zeros (h_{-1} = 0) ----
    {
        const uint4 z = make_uint4(0u, 0u, 0u, 0u);
        for (int i = tid; i < BB * 32; i += NTHR) {
            int b = i >> 5, c = i & 31;
            uint32_t d = (uint32_t)(BOFF + b * BSTRIDE + c * 16);
            *(uint4*)(sm + d)        = z;
            *(uint4*)(sm + d + TSZB) = z;
        }
    }
    __syncthreads();

    for (int t = 0; t < TT; t++) {
        // ---- MMA: warp = 16j x 32b; 3 terms, K=256 (16 kc, fully unrolled) ----
        float acc[4][4];
#pragma unroll
        for (int nf = 0; nf < 4; nf++)
#pragma unroll
            for (int i = 0; i < 4; i++) acc[nf][i] = 0.0f;

#pragma unroll 4
        for (int kc = 0; kc < 16; kc++) {
            const uint32_t ka = (uint32_t)kc * 32;
            uint32_t Ah[4], Al[4], Bh[2][4], Bl[2][4];
            ldmx4(Ah, aA + ka);
            ldmx4(Al, aA + TSZA + ka);
            ldmx4(Bh[0], aB + ka);
            ldmx4(Bh[1], aB + 16 * BSTRIDE + ka);
            ldmx4(Bl[0], aB + TSZB + ka);
            ldmx4(Bl[1], aB + TSZB + 16 * BSTRIDE + ka);
#pragma unroll
            for (int nf = 0; nf < 4; nf++) {
                const int ni = nf >> 1, h8 = (nf & 1) * 2;
                mma_bf16(acc[nf], Ah, Bh[ni][h8], Bh[ni][h8 + 1]);
                mma_bf16(acc[nf], Ah, Bl[ni][h8], Bl[ni][h8 + 1]);
                mma_bf16(acc[nf], Al, Bh[ni][h8], Bh[ni][h8 + 1]);
            }
        }

        // ---- partial stores (.cg) into ping-pong buffer: P[jl*64 + b] ----
        {
            float* P = g_part[t & 1] + (unsigned)(ks * NJG + jg) * (128 * BB);
            const int j0 = wj * 16 + (l >> 2);
            const int bc = (l & 3) * 2;
#pragma unroll
            for (int nf = 0; nf < 4; nf++) {
                const int b = wb * 32 + nf * 8 + bc;
                __stcg((float2*)&P[j0 * BB + b],       make_float2(acc[nf][0], acc[nf][1]));
                __stcg((float2*)&P[(j0 + 8) * BB + b], make_float2(acc[nf][2], acc[nf][3]));
            }
        }
        __syncthreads();                        // all P stores + all v reads done
        if (tid == 0) flag_add(&g_pcnt[jg]);

        // ---- reduce role (all 128 CTAs): 16j x 64b tile; xc first, then ks 0..7 ----
        {
            if (tid == 0) spin_ge(&g_pcnt[r_jg], 8u * (t + 1));
            __syncthreads();

            const unsigned o = (unsigned)((r_8 * 16 + jt) * 64 + b2);
            const float2 xv = *(const float2*)
                (g_xc + (unsigned)(t * NJG + r_jg) * (128 * BB) + o);
            float s0 = xv.x, s1 = xv.y;
            const float* Pb = g_part[t & 1];
#pragma unroll
            for (int kr = 0; kr < NKS; kr++) {
                const float2 v = __ldcg((const float2*)
                    (Pb + (unsigned)(kr * NJG + r_jg) * (128 * BB) + o));
                s0 += v.x; s1 += v.y;
            }
            s0 = tanhf(s0); s1 = tanhf(s1);
            sT[jt * 65 + b2]     = s0;
            sT[jt * 65 + b2 + 1] = s1;
            __syncthreads();                    // transpose handoff

            __nv_bfloat16* hh = g_hh[t & 1];
            __nv_bfloat16* hl = g_hl[t & 1];
            const bool last_t = (t == TT - 1);
            {
                const int p  = tid & 7;         // j pair
                const int bb = tid >> 3;        // batch
                const float f0 = sT[(2 * p) * 65 + bb];
                const float f1 = sT[(2 * p + 1) * 65 + bb];
                const int jglob = r_jg * 128 + r_8 * 16 + 2 * p;
                __nv_bfloat162 h2 = __floats2bfloat162_rn(f0, f1);
                float r0 = f0 - __bfloat162float(__low2bfloat16(h2));
                float r1 = f1 - __bfloat162float(__high2bfloat16(h2));
                __nv_bfloat162 l2 = __floats2bfloat162_rn(r0, r1);
                __stcg((unsigned*)(hh + bb * HH + jglob), *(unsigned*)&h2);
                __stcg((unsigned*)(hl + bb * HH + jglob), *(unsigned*)&l2);
                if (last_t) *(float2*)&out[bb * HH + jglob] = make_float2(f0, f1);
            }
            __syncthreads();                    // all h stores done before flag
            if (tid == 0) flag_add(&g_hfl[r_jg]);
        }

        // ---- stage v_{t+1} = h_t slice ks ----
        if (t + 1 < TT) {
            if (tid == 0) {
                if (t >= 1) spin_ge(&g_hfl[jg], 8u * t);   // P WAR (ping-pong)
                spin_ge(&g_hfl[2 * ks],     8u * (t + 1)); // RAW: slice halves
                spin_ge(&g_hfl[2 * ks + 1], 8u * (t + 1));
            }
            __syncthreads();

            const __nv_bfloat16* hh = g_hh[t & 1];
            const __nv_bfloat16* hl = g_hl[t & 1];
#pragma unroll
            for (int it = 0; it < 4; it++) {
                int i = it * NTHR + tid;
                int b = i >> 5, c = i & 31;
                int e = b * HH + ks * KC1 + c * 8;
                uint32_t d = (uint32_t)(BOFF + b * BSTRIDE + c * 16);
                *(uint4*)(sm + d)        = __ldcg((const uint4*)(hh + e));
                *(uint4*)(sm + d + TSZB) = __ldcg((const uint4*)(hl + e));
            }
            __syncthreads();                    // v staged before next MMA
        }
    }
}

// ---------------- launcher ----------------
extern "C" void kernel_launch(void* const* d_in, const int* in_sizes, int n_in,
                              void* d_out, int out_size)
{
    const float* x    = (const float*)d_in[0];
    const float* Win  = (const float*)d_in[1];
    const float* Wres = (const float*)d_in[2];
    float* out = (float*)d_out;

    cudaFuncSetAttribute(esn_run, cudaFuncAttributeMaxDynamicSharedMemorySize, DYN_SMEM);
    cudaFuncSetAttribute(esn_prep_xc, cudaFuncAttributeMaxDynamicSharedMemorySize, DYN2);

    esn_prep_w<<<2048, 256>>>(Win, Wres);
    esn_prep_x<<<2048, 256>>>(x);
    esn_prep_xc<<<TT * NJG, NTHR, DYN2>>>();
    esn_cnt0<<<1, 32>>>();
    esn_run<<<NCTA, NTHR, DYN_SMEM>>>(out);
}

// round 14
// speedup vs baseline: 1.9110x; 1.0880x over previous
#include <cuda_runtime.h>
#include <cuda_bf16.h>
#include <cstdint>

// ESN: h_t = tanh(x_t @ W_in^T + h_{t-1} @ W_res^T); out = h_{T-1} [B,H] fp32.
// B=64, T=512, I=128, H=2048.
//
// Round 14: round-9 chassis (persistent 144 CTAs, 3-term bf16 mma.sync,
// 16 warps 16j x 32b, W in smem, WIDE 128-CTA reduce, P ping-pong, R7 flag
// layer) merged with round-11's verified transposed activation layout:
//  - h stored [j][b] (h^T), x pre-transposed [t][k][b]
//  - reducer: P-read index == h-store index -> no smem transpose, one less bar
//  - stager: contiguous 128B row reads; B frags via ldmatrix.x4.trans.

#define BB   64
#define TT   512
#define II   128
#define HH   2048
#define NJG  16
#define NKS  9
#define KC1  256
#define NTHR 512
#define NCTA (NJG * NKS)          // 144
#define ASTRIDE 528               // bytes per j-row of W tiles (512 + 16 pad)
#define TSZA (128 * ASTRIDE)      // 67584 per W term
#define BSTR 144                  // bytes per k-row of v (128 data + 16 pad)
#define TSZB (256 * BSTR)         // 36864 per v term (max 256 k-rows)
#define BOFF (2 * TSZA)
#define SLOT (2 * TSZA)
#define DYN_SMEM (2 * TSZA + 2 * TSZB)   // 208896

// ---------------- device globals ----------------
__device__ __align__(16) unsigned char  g_wt[NCTA * SLOT];
__device__ __align__(16) __nv_bfloat16  g_xth[TT * II * BB];   // x^T hi: [t][k][b]
__device__ __align__(16) __nv_bfloat16  g_xtl[TT * II * BB];   // x^T lo
__device__ __align__(16) __nv_bfloat16  g_hth[2][HH * BB];     // h^T hi: [j][b]
__device__ __align__(16) __nv_bfloat16  g_htl[2][HH * BB];     // h^T lo
__device__ float    g_part[2][NKS * NJG * 128 * BB];           // ping-pong by t&1
__device__ unsigned g_pcnt[NJG];   // partials stored, per jg (9/step)
__device__ unsigned g_hfl[8];      // h slice ready, per 256j slice (16/step)

// ---------------- asm helpers ----------------
__device__ __forceinline__ void mma_bf16(float* d, const uint32_t* a,
                                         uint32_t b0, uint32_t b1) {
    asm volatile(
        "mma.sync.aligned.m16n8k16.row.col.f32.bf16.bf16.f32 "
        "{%0,%1,%2,%3}, {%4,%5,%6,%7}, {%8,%9}, {%0,%1,%2,%3};"
        : "+f"(d[0]), "+f"(d[1]), "+f"(d[2]), "+f"(d[3])
        : "r"(a[0]), "r"(a[1]), "r"(a[2]), "r"(a[3]), "r"(b0), "r"(b1));
}
__device__ __forceinline__ void ldmx4(uint32_t* r, uint32_t addr) {
    asm volatile("ldmatrix.sync.aligned.m8n8.x4.shared.b16 {%0,%1,%2,%3}, [%4];"
        : "=r"(r[0]), "=r"(r[1]), "=r"(r[2]), "=r"(r[3]) : "r"(addr));
}
__device__ __forceinline__ void ldmx4t(uint32_t* r, uint32_t addr) {
    asm volatile("ldmatrix.sync.aligned.m8n8.x4.trans.shared.b16 {%0,%1,%2,%3}, [%4];"
        : "=r"(r[0]), "=r"(r[1]), "=r"(r[2]), "=r"(r[3]) : "r"(addr));
}
__device__ __forceinline__ uint32_t smem_u32(const void* p) {
    uint32_t a;
    asm("{ .reg .u64 t; cvta.to.shared.u64 t, %1; cvt.u32.u64 %0, t; }"
        : "=r"(a) : "l"(p));
    return a;
}
__device__ __forceinline__ void flag_add(unsigned* p) {
    asm volatile("red.release.gpu.global.add.u32 [%0], 1;" :: "l"(p) : "memory");
}
__device__ __forceinline__ void spin_ge(unsigned* c, unsigned tgt) {
    unsigned v;
    do {
        asm volatile("ld.acquire.gpu.global.u32 %0, [%1];"
                     : "=r"(v) : "l"(c) : "memory");
    } while (v < tgt);
}

// ---------------- prep ----------------
__global__ void esn_prep_w(const float* __restrict__ Win, const float* __restrict__ Wres) {
    const int total = HH * (II + HH);
    for (int idx = blockIdx.x * blockDim.x + threadIdx.x; idx < total;
         idx += gridDim.x * blockDim.x) {
        int j = idx / (II + HH);
        int k = idx % (II + HH);
        int jg = j >> 7, jl = j & 127;
        int ks, kl;
        float w;
        if (k < II) { ks = 0; kl = k; w = Win[j * II + k]; }
        else { int kk = k - II; ks = 1 + (kk >> 8); kl = kk & 255; w = Wres[j * HH + kk]; }
        __nv_bfloat16 hi = __float2bfloat16(w);
        float r = w - __bfloat162float(hi);
        __nv_bfloat16 lo = __float2bfloat16(r);
        unsigned base = (unsigned)(jg * NKS + ks) * SLOT + (unsigned)jl * ASTRIDE + (unsigned)kl * 2;
        *(__nv_bfloat16*)(g_wt + base)        = hi;
        *(__nv_bfloat16*)(g_wt + base + TSZA) = lo;
    }
}

// x -> transposed [t][k][b] bf16 hi/lo planes (verified in round 11)
__global__ void esn_prep_x(const float* __restrict__ x) {
    const int total = TT * II * BB;
    for (int idx = blockIdx.x * blockDim.x + threadIdx.x; idx < total;
         idx += gridDim.x * blockDim.x) {
        int b  = idx & (BB - 1);
        int tk = idx / BB;
        int t  = tk / II;
        int k  = tk % II;
        float v = x[(b * TT + t) * II + k];
        __nv_bfloat16 hi = __float2bfloat16(v);
        float r = v - __bfloat162float(hi);
        g_xth[idx] = hi;
        g_xtl[idx] = __float2bfloat16(r);
    }
}

__global__ void esn_cnt0() {
    int i = threadIdx.x;
    if (i < NJG) g_pcnt[i] = 0u;
    if (i < 8)  g_hfl[i] = 0u;
}

// ---------------- persistent kernel ----------------
__global__ __launch_bounds__(NTHR, 1) void esn_run(float* __restrict__ out) {
    extern __shared__ __align__(16) unsigned char sm[];

    const int tid  = threadIdx.x;
    const int wid  = tid >> 5;
    const int l    = tid & 31;
    const int wj   = wid >> 1;            // 0..7: 16-row j band
    const int wb   = wid & 1;             // 0..1: 32-col b half
    const int bid  = blockIdx.x;
    const int jg   = bid / NKS;
    const int ks   = bid % NKS;
    const int KC   = ks ? KC1 : II;
    const int kch  = KC >> 4;             // 8 or 16
    const int chunks = KC * 8;            // 16B chunks (8 per 128B k-row)

    const uint32_t smA = smem_u32(sm);
    const uint32_t smB = smA + BOFF;

    // A ldmatrix lane base (normal, [j][k] rows)
    const uint32_t aA = smA + (uint32_t)(wj * 16 + ((l >> 3) & 1) * 8 + (l & 7)) * ASTRIDE
                            + (uint32_t)(l >> 4) * 16;
    // B ldmatrix.trans lane base ([k][b] rows) — verified in round 11
    const uint32_t aB = smB + (uint32_t)((l & 7) + ((l >> 3) & 1) * 8) * BSTR
                            + (uint32_t)(l >> 4) * 16 + (uint32_t)wb * 64;

    // ---- load W slot (hi + lo) into smem once ----
    {
        const uint4* src = (const uint4*)(g_wt + (unsigned)(jg * NKS + ks) * SLOT);
        uint4* dst = (uint4*)sm;
        for (int i = tid; i < SLOT / 16; i += NTHR) dst[i] = src[i];
    }

    // reduce-role constants (bid 0..127): 16j x 64b tile
    const int r_jg = bid >> 3;
    const int r_8  = bid & 7;
    const int r_s  = r_jg >> 1;
    const int jt   = tid >> 5;             // 0..15
    const int b2   = (tid & 31) * 2;       // 0..62

    // ---- stage v_0: ks==0 from x^T[0], else zeros (h_{-1} = 0) ----
    if (ks == 0) {
        for (int i = tid; i < chunks; i += NTHR) {
            int k = i >> 3, c = i & 7;
            uint32_t d = (uint32_t)(BOFF + k * BSTR + c * 16);
            int e = k * BB + c * 8;        // t=0 base
            *(uint4*)(sm + d)        = *(const uint4*)(g_xth + e);
            *(uint4*)(sm + d + TSZB) = *(const uint4*)(g_xtl + e);
        }
    } else {
        const uint4 z = make_uint4(0u, 0u, 0u, 0u);
        for (int i = tid; i < chunks; i += NTHR) {
            int k = i >> 3, c = i & 7;
            uint32_t d = (uint32_t)(BOFF + k * BSTR + c * 16);
            *(uint4*)(sm + d)        = z;
            *(uint4*)(sm + d + TSZB) = z;
        }
    }
    __syncthreads();

    for (int t = 0; t < TT; t++) {
        // ---- MMA: warp = 16j x 32b; 3 terms (Ah*Bh + Ah*Bl + Al*Bh) ----
        float acc[4][4];
#pragma unroll
        for (int nf = 0; nf < 4; nf++)
#pragma unroll
            for (int i = 0; i < 4; i++) acc[nf][i] = 0.0f;

#pragma unroll 4
        for (int kc = 0; kc < kch; kc++) {
            const uint32_t kaA = (uint32_t)kc * 32;
            const uint32_t kaB = (uint32_t)kc * (16 * BSTR);
            uint32_t Ah[4], Al[4], Bh[2][4], Bl[2][4];
            ldmx4(Ah, aA + kaA);
            ldmx4(Al, aA + TSZA + kaA);
            ldmx4t(Bh[0], aB + kaB);
            ldmx4t(Bh[1], aB + kaB + 32);
            ldmx4t(Bl[0], aB + TSZB + kaB);
            ldmx4t(Bl[1], aB + TSZB + kaB + 32);
#pragma unroll
            for (int nf = 0; nf < 4; nf++) {
                const int ni = nf >> 1, h8 = (nf & 1) * 2;
                mma_bf16(acc[nf], Ah, Bh[ni][h8], Bh[ni][h8 + 1]);
                mma_bf16(acc[nf], Ah, Bl[ni][h8], Bl[ni][h8 + 1]);
                mma_bf16(acc[nf], Al, Bh[ni][h8], Bh[ni][h8 + 1]);
            }
        }

        // ---- partial stores (.cg) into ping-pong buffer: P[jl*64 + b] ----
        {
            float* P = g_part[t & 1] + (unsigned)(ks * NJG + jg) * (128 * BB);
            const int j0 = wj * 16 + (l >> 2);
            const int bc = (l & 3) * 2;
#pragma unroll
            for (int nf = 0; nf < 4; nf++) {
                const int b = wb * 32 + nf * 8 + bc;
                __stcg((float2*)&P[j0 * BB + b],       make_float2(acc[nf][0], acc[nf][1]));
                __stcg((float2*)&P[(j0 + 8) * BB + b], make_float2(acc[nf][2], acc[nf][3]));
            }
        }
        __syncthreads();                        // all P stores + all v reads done
        if (tid == 0) flag_add(&g_pcnt[jg]);

        // ---- reduce role (bid 0..127): 16j x 64b tile, NO transpose ----
        if (bid < 128) {
            if (tid == 0) spin_ge(&g_pcnt[r_jg], 9u * (t + 1));
            __syncthreads();

            const unsigned o = (unsigned)((r_8 * 16 + jt) * 64 + b2);
            float s0 = 0.f, s1 = 0.f;
            const float* Pb = g_part[t & 1];
#pragma unroll
            for (int kr = 0; kr < NKS; kr++) {
                const float2 v = __ldcg((const float2*)
                    (Pb + (unsigned)(kr * NJG + r_jg) * (128 * BB) + o));
                s0 += v.x; s1 += v.y;
            }
            s0 = tanhf(s0); s1 = tanhf(s1);

            // h^T store: index == P index (coalesced: b2 = lane*2)
            __nv_bfloat16* hh = g_hth[t & 1];
            __nv_bfloat16* hl = g_htl[t & 1];
            const int jglob = r_jg * 128 + r_8 * 16 + jt;
            const unsigned ho = (unsigned)(jglob * BB + b2);
            __nv_bfloat162 h2 = __floats2bfloat162_rn(s0, s1);
            float r0 = s0 - __bfloat162float(__low2bfloat16(h2));
            float r1 = s1 - __bfloat162float(__high2bfloat16(h2));
            __nv_bfloat162 l2 = __floats2bfloat162_rn(r0, r1);
            __stcg((unsigned*)(hh + ho), *(unsigned*)&h2);
            __stcg((unsigned*)(hl + ho), *(unsigned*)&l2);
            if (t == TT - 1) {                  // one-time scattered out store
                out[b2 * HH + jglob]       = s0;
                out[(b2 + 1) * HH + jglob] = s1;
            }
            __syncthreads();                    // all h stores done before flag
            if (tid == 0) flag_add(&g_hfl[r_s]);
        }

        // ---- stage v_{t+1} (contiguous 128B k-rows) ----
        if (t + 1 < TT) {
            if (tid == 0) {
                // P WAR: reducers of my jg done reading P[(t+1)&1] (step t-1)
                if (t >= 1) spin_ge(&g_hfl[jg >> 1], 16u * t);
                // RAW: h_t slice ready
                if (ks) spin_ge(&g_hfl[ks - 1], 16u * (t + 1));
            }
            __syncthreads();

            if (ks == 0) {
                const __nv_bfloat16* xh = g_xth + (t + 1) * (II * BB);
                const __nv_bfloat16* xl = g_xtl + (t + 1) * (II * BB);
                for (int i = tid; i < chunks; i += NTHR) {
                    int k = i >> 3, c = i & 7;
                    uint32_t d = (uint32_t)(BOFF + k * BSTR + c * 16);
                    int e = k * BB + c * 8;
                    *(uint4*)(sm + d)        = *(const uint4*)(xh + e);
                    *(uint4*)(sm + d + TSZB) = *(const uint4*)(xl + e);
                }
            } else {
                const __nv_bfloat16* hh = g_hth[t & 1] + (ks - 1) * (KC1 * BB);
                const __nv_bfloat16* hl = g_htl[t & 1] + (ks - 1) * (KC1 * BB);
                for (int i = tid; i < chunks; i += NTHR) {
                    int k = i >> 3, c = i & 7;
                    uint32_t d = (uint32_t)(BOFF + k * BSTR + c * 16);
                    int e = k * BB + c * 8;
                    *(uint4*)(sm + d)        = __ldcg((const uint4*)(hh + e));
                    *(uint4*)(sm + d + TSZB) = __ldcg((const uint4*)(hl + e));
                }
            }
            __syncthreads();                    // v staged before next MMA
        }
    }
}

// ---------------- launcher ----------------
extern "C" void kernel_launch(void* const* d_in, const int* in_sizes, int n_in,
                              void* d_out, int out_size)
{
    const float* x    = (const float*)d_in[0];
    const float* Win  = (const float*)d_in[1];
    const float* Wres = (const float*)d_in[2];
    float* out = (float*)d_out;

    cudaFuncSetAttribute(esn_run, cudaFuncAttributeMaxDynamicSharedMemorySize, DYN_SMEM);

    esn_prep_w<<<2048, 256>>>(Win, Wres);
    esn_prep_x<<<2048, 256>>>(x);
    esn_cnt0<<<1, 32>>>();
    esn_run<<<NCTA, NTHR, DYN_SMEM>>>(out);
}

// round 15
// speedup vs baseline: 1.9888x; 1.0407x over previous
#include <cuda_runtime.h>
#include <cuda_bf16.h>
#include <cstdint>

// ESN: h_t = tanh(x_t @ W_in^T + h_{t-1} @ W_res^T); out = h_{T-1} [B,H] fp32.
// B=64, T=512, I=128, H=2048.
//
// Round 15: round-14 chassis (persistent 144 CTAs, 3-term bf16 mma.sync,
// 16 warps 16j x 32b, W in smem, wide reduce, h^T layout, ldmatrix.trans)
// with contention micro-cuts:
//  - every sync flag padded to its own 128B L2 sector (was: 16 flags/line)
//  - all-thread ld.acquire spins at wait points (no tid0-spin + bar wake).

#define BB   64
#define TT   512
#define II   128
#define HH   2048
#define NJG  16
#define NKS  9
#define KC1  256
#define NTHR 512
#define NCTA (NJG * NKS)          // 144
#define ASTRIDE 528               // bytes per j-row of W tiles (512 + 16 pad)
#define TSZA (128 * ASTRIDE)      // 67584 per W term
#define BSTR 144                  // bytes per k-row of v (128 data + 16 pad)
#define TSZB (256 * BSTR)         // 36864 per v term (max 256 k-rows)
#define BOFF (2 * TSZA)
#define SLOT (2 * TSZA)
#define DYN_SMEM (2 * TSZA + 2 * TSZB)   // 208896

// ---------------- device globals ----------------
struct __align__(128) PadFlag { unsigned v; unsigned pad[31]; };

__device__ __align__(16) unsigned char  g_wt[NCTA * SLOT];
__device__ __align__(16) __nv_bfloat16  g_xth[TT * II * BB];   // x^T hi: [t][k][b]
__device__ __align__(16) __nv_bfloat16  g_xtl[TT * II * BB];   // x^T lo
__device__ __align__(16) __nv_bfloat16  g_hth[2][HH * BB];     // h^T hi: [j][b]
__device__ __align__(16) __nv_bfloat16  g_htl[2][HH * BB];     // h^T lo
__device__ float    g_part[2][NKS * NJG * 128 * BB];           // ping-pong by t&1
__device__ PadFlag  g_pcnt[NJG];   // partials stored, per jg (9/step)
__device__ PadFlag  g_hfl[8];      // h slice ready, per 256j slice (16/step)

// ---------------- asm helpers ----------------
__device__ __forceinline__ void mma_bf16(float* d, const uint32_t* a,
                                         uint32_t b0, uint32_t b1) {
    asm volatile(
        "mma.sync.aligned.m16n8k16.row.col.f32.bf16.bf16.f32 "
        "{%0,%1,%2,%3}, {%4,%5,%6,%7}, {%8,%9}, {%0,%1,%2,%3};"
        : "+f"(d[0]), "+f"(d[1]), "+f"(d[2]), "+f"(d[3])
        : "r"(a[0]), "r"(a[1]), "r"(a[2]), "r"(a[3]), "r"(b0), "r"(b1));
}
__device__ __forceinline__ void ldmx4(uint32_t* r, uint32_t addr) {
    asm volatile("ldmatrix.sync.aligned.m8n8.x4.shared.b16 {%0,%1,%2,%3}, [%4];"
        : "=r"(r[0]), "=r"(r[1]), "=r"(r[2]), "=r"(r[3]) : "r"(addr));
}
__device__ __forceinline__ void ldmx4t(uint32_t* r, uint32_t addr) {
    asm volatile("ldmatrix.sync.aligned.m8n8.x4.trans.shared.b16 {%0,%1,%2,%3}, [%4];"
        : "=r"(r[0]), "=r"(r[1]), "=r"(r[2]), "=r"(r[3]) : "r"(addr));
}
__device__ __forceinline__ uint32_t smem_u32(const void* p) {
    uint32_t a;
    asm("{ .reg .u64 t; cvta.to.shared.u64 t, %1; cvt.u32.u64 %0, t; }"
        : "=r"(a) : "l"(p));
    return a;
}
__device__ __forceinline__ void flag_add(unsigned* p) {
    asm volatile("red.release.gpu.global.add.u32 [%0], 1;" :: "l"(p) : "memory");
}
// all-thread acquire spin: after return, this thread's later loads are ordered
__device__ __forceinline__ void spin_ge(unsigned* c, unsigned tgt) {
    unsigned v;
    do {
        asm volatile("ld.acquire.gpu.global.u32 %0, [%1];"
                     : "=r"(v) : "l"(c) : "memory");
    } while (v < tgt);
}

// ---------------- prep ----------------
__global__ void esn_prep_w(const float* __restrict__ Win, const float* __restrict__ Wres) {
    const int total = HH * (II + HH);
    for (int idx = blockIdx.x * blockDim.x + threadIdx.x; idx < total;
         idx += gridDim.x * blockDim.x) {
        int j = idx / (II + HH);
        int k = idx % (II + HH);
        int jg = j >> 7, jl = j & 127;
        int ks, kl;
        float w;
        if (k < II) { ks = 0; kl = k; w = Win[j * II + k]; }
        else { int kk = k - II; ks = 1 + (kk >> 8); kl = kk & 255; w = Wres[j * HH + kk]; }
        __nv_bfloat16 hi = __float2bfloat16(w);
        float r = w - __bfloat162float(hi);
        __nv_bfloat16 lo = __float2bfloat16(r);
        unsigned base = (unsigned)(jg * NKS + ks) * SLOT + (unsigned)jl * ASTRIDE + (unsigned)kl * 2;
        *(__nv_bfloat16*)(g_wt + base)        = hi;
        *(__nv_bfloat16*)(g_wt + base + TSZA) = lo;
    }
}

// x -> transposed [t][k][b] bf16 hi/lo planes
__global__ void esn_prep_x(const float* __restrict__ x) {
    const int total = TT * II * BB;
    for (int idx = blockIdx.x * blockDim.x + threadIdx.x; idx < total;
         idx += gridDim.x * blockDim.x) {
        int b  = idx & (BB - 1);
        int tk = idx / BB;
        int t  = tk / II;
        int k  = tk % II;
        float v = x[(b * TT + t) * II + k];
        __nv_bfloat16 hi = __float2bfloat16(v);
        float r = v - __bfloat162float(hi);
        g_xth[idx] = hi;
        g_xtl[idx] = __float2bfloat16(r);
    }
}

__global__ void esn_cnt0() {
    int i = threadIdx.x;
    if (i < NJG) g_pcnt[i].v = 0u;
    if (i < 8)  g_hfl[i].v = 0u;
}

// ---------------- persistent kernel ----------------
__global__ __launch_bounds__(NTHR, 1) void esn_run(float* __restrict__ out) {
    extern __shared__ __align__(16) unsigned char sm[];

    const int tid  = threadIdx.x;
    const int wid  = tid >> 5;
    const int l    = tid & 31;
    const int wj   = wid >> 1;            // 0..7: 16-row j band
    const int wb   = wid & 1;             // 0..1: 32-col b half
    const int bid  = blockIdx.x;
    const int jg   = bid / NKS;
    const int ks   = bid % NKS;
    const int KC   = ks ? KC1 : II;
    const int kch  = KC >> 4;             // 8 or 16
    const int chunks = KC * 8;            // 16B chunks (8 per 128B k-row)

    const uint32_t smA = smem_u32(sm);
    const uint32_t smB = smA + BOFF;

    const uint32_t aA = smA + (uint32_t)(wj * 16 + ((l >> 3) & 1) * 8 + (l & 7)) * ASTRIDE
                            + (uint32_t)(l >> 4) * 16;
    const uint32_t aB = smB + (uint32_t)((l & 7) + ((l >> 3) & 1) * 8) * BSTR
                            + (uint32_t)(l >> 4) * 16 + (uint32_t)wb * 64;

    // ---- load W slot (hi + lo) into smem once ----
    {
        const uint4* src = (const uint4*)(g_wt + (unsigned)(jg * NKS + ks) * SLOT);
        uint4* dst = (uint4*)sm;
        for (int i = tid; i < SLOT / 16; i += NTHR) dst[i] = src[i];
    }

    // reduce-role constants (bid 0..127): 16j x 64b tile
    const int r_jg = bid >> 3;
    const int r_8  = bid & 7;
    const int r_s  = r_jg >> 1;
    const int jt   = tid >> 5;             // 0..15
    const int b2   = (tid & 31) * 2;       // 0..62

    // ---- stage v_0: ks==0 from x^T[0], else zeros (h_{-1} = 0) ----
    if (ks == 0) {
        for (int i = tid; i < chunks; i += NTHR) {
            int k = i >> 3, c = i & 7;
            uint32_t d = (uint32_t)(BOFF + k * BSTR + c * 16);
            int e = k * BB + c * 8;
            *(uint4*)(sm + d)        = *(const uint4*)(g_xth + e);
            *(uint4*)(sm + d + TSZB) = *(const uint4*)(g_xtl + e);
        }
    } else {
        const uint4 z = make_uint4(0u, 0u, 0u, 0u);
        for (int i = tid; i < chunks; i += NTHR) {
            int k = i >> 3, c = i & 7;
            uint32_t d = (uint32_t)(BOFF + k * BSTR + c * 16);
            *(uint4*)(sm + d)        = z;
            *(uint4*)(sm + d + TSZB) = z;
        }
    }
    __syncthreads();

    for (int t = 0; t < TT; t++) {
        // ---- MMA: warp = 16j x 32b; 3 terms (Ah*Bh + Ah*Bl + Al*Bh) ----
        float acc[4][4];
#pragma unroll
        for (int nf = 0; nf < 4; nf++)
#pragma unroll
            for (int i = 0; i < 4; i++) acc[nf][i] = 0.0f;

#pragma unroll 4
        for (int kc = 0; kc < kch; kc++) {
            const uint32_t kaA = (uint32_t)kc * 32;
            const uint32_t kaB = (uint32_t)kc * (16 * BSTR);
            uint32_t Ah[4], Al[4], Bh[2][4], Bl[2][4];
            ldmx4(Ah, aA + kaA);
            ldmx4(Al, aA + TSZA + kaA);
            ldmx4t(Bh[0], aB + kaB);
            ldmx4t(Bh[1], aB + kaB + 32);
            ldmx4t(Bl[0], aB + TSZB + kaB);
            ldmx4t(Bl[1], aB + TSZB + kaB + 32);
#pragma unroll
            for (int nf = 0; nf < 4; nf++) {
                const int ni = nf >> 1, h8 = (nf & 1) * 2;
                mma_bf16(acc[nf], Ah, Bh[ni][h8], Bh[ni][h8 + 1]);
                mma_bf16(acc[nf], Ah, Bl[ni][h8], Bl[ni][h8 + 1]);
                mma_bf16(acc[nf], Al, Bh[ni][h8], Bh[ni][h8 + 1]);
            }
        }

        // ---- partial stores (.cg) into ping-pong buffer: P[jl*64 + b] ----
        {
            float* P = g_part[t & 1] + (unsigned)(ks * NJG + jg) * (128 * BB);
            const int j0 = wj * 16 + (l >> 2);
            const int bc = (l & 3) * 2;
#pragma unroll
            for (int nf = 0; nf < 4; nf++) {
                const int b = wb * 32 + nf * 8 + bc;
                __stcg((float2*)&P[j0 * BB + b],       make_float2(acc[nf][0], acc[nf][1]));
                __stcg((float2*)&P[(j0 + 8) * BB + b], make_float2(acc[nf][2], acc[nf][3]));
            }
        }
        __syncthreads();                        // all P stores + all v reads done
        if (tid == 0) flag_add(&g_pcnt[jg].v);

        // ---- reduce role (bid 0..127): 16j x 64b tile, all-thread spin ----
        if (bid < 128) {
            spin_ge(&g_pcnt[r_jg].v, 9u * (t + 1));   // acquire orders my loads

            const unsigned o = (unsigned)((r_8 * 16 + jt) * 64 + b2);
            float s0 = 0.f, s1 = 0.f;
            const float* Pb = g_part[t & 1];
#pragma unroll
            for (int kr = 0; kr < NKS; kr++) {
                const float2 v = __ldcg((const float2*)
                    (Pb + (unsigned)(kr * NJG + r_jg) * (128 * BB) + o));
                s0 += v.x; s1 += v.y;
            }
            s0 = tanhf(s0); s1 = tanhf(s1);

            __nv_bfloat16* hh = g_hth[t & 1];
            __nv_bfloat16* hl = g_htl[t & 1];
            const int jglob = r_jg * 128 + r_8 * 16 + jt;
            const unsigned ho = (unsigned)(jglob * BB + b2);
            __nv_bfloat162 h2 = __floats2bfloat162_rn(s0, s1);
            float r0 = s0 - __bfloat162float(__low2bfloat16(h2));
            float r1 = s1 - __bfloat162float(__high2bfloat16(h2));
            __nv_bfloat162 l2 = __floats2bfloat162_rn(r0, r1);
            __stcg((unsigned*)(hh + ho), *(unsigned*)&h2);
            __stcg((unsigned*)(hl + ho), *(unsigned*)&l2);
            if (t == TT - 1) {                  // one-time scattered out store
                out[b2 * HH + jglob]       = s0;
                out[(b2 + 1) * HH + jglob] = s1;
            }
            __syncthreads();                    // all h stores done before flag
            if (tid == 0) flag_add(&g_hfl[r_s].v);
        }

        // ---- stage v_{t+1} (contiguous 128B k-rows), all-thread spins ----
        if (t + 1 < TT) {
            // P WAR: reducers of my jg done reading P[(t+1)&1] (step t-1)
            if (t >= 1) spin_ge(&g_hfl[jg >> 1].v, 16u * t);
            // RAW: h_t slice ready
            if (ks) spin_ge(&g_hfl[ks - 1].v, 16u * (t + 1));

            if (ks == 0) {
                const __nv_bfloat16* xh = g_xth + (t + 1) * (II * BB);
                const __nv_bfloat16* xl = g_xtl + (t + 1) * (II * BB);
                for (int i = tid; i < chunks; i += NTHR) {
                    int k = i >> 3, c = i & 7;
                    uint32_t d = (uint32_t)(BOFF + k * BSTR + c * 16);
                    int e = k * BB + c * 8;
                    *(uint4*)(sm + d)        = *(const uint4*)(xh + e);
                    *(uint4*)(sm + d + TSZB) = *(const uint4*)(xl + e);
                }
            } else {
                const __nv_bfloat16* hh = g_hth[t & 1] + (ks - 1) * (KC1 * BB);
                const __nv_bfloat16* hl = g_htl[t & 1] + (ks - 1) * (KC1 * BB);
                for (int i = tid; i < chunks; i += NTHR) {
                    int k = i >> 3, c = i & 7;
                    uint32_t d = (uint32_t)(BOFF + k * BSTR + c * 16);
                    int e = k * BB + c * 8;
                    *(uint4*)(sm + d)        = __ldcg((const uint4*)(hh + e));
                    *(uint4*)(sm + d + TSZB) = __ldcg((const uint4*)(hl + e));
                }
            }
            __syncthreads();                    // v staged before next MMA
        }
    }
}

// ---------------- launcher ----------------
extern "C" void kernel_launch(void* const* d_in, const int* in_sizes, int n_in,
                              void* d_out, int out_size)
{
    const float* x    = (const float*)d_in[0];
    const float* Win  = (const float*)d_in[1];
    const float* Wres = (const float*)d_in[2];
    float* out = (float*)d_out;

    cudaFuncSetAttribute(esn_run, cudaFuncAttributeMaxDynamicSharedMemorySize, DYN_SMEM);

    esn_prep_w<<<2048, 256>>>(Win, Wres);
    esn_prep_x<<<2048, 256>>>(x);
    esn_cnt0<<<1, 32>>>();
    esn_run<<<NCTA, NTHR, DYN_SMEM>>>(out);
}